// round 16
// baseline (speedup 1.0000x reference)
#include <cuda_runtime.h>
#include <cuda_fp16.h>
#include <math.h>
#include <stdint.h>

// Problem constants
#define RTOT 8192     // QB*N tokens
#define DIMM 1024
#define HH 8
#define DD 128
#define NN 512
#define QBB 16
#define GCH 16        // gram split-K chunks (512 rows each)

// ---------------- static device scratch (no runtime allocation) ----------------
__device__ __half d_xh[3][RTOT * DIMM];   // LN(x) hi fp16 (q,k,v)
__device__ __half d_xl[3][RTOT * DIMM];   // LN(x) lo residual
__device__ __half d_oh[RTOT * DIMM];      // att output hi
__device__ __half d_ol[RTOT * DIMM];      // att output lo
__device__ __half d_wih[DIMM * DIMM];     // w_in hi (2-term GEMM)
__device__ __half d_woh[DIMM * DIMM];     // w_out hi (2-term GEMM)
__device__ __half d_fqh[RTOT * DIMM], d_fql[RTOT * DIMM];  // f_q split
__device__ __half d_fkh[RTOT * DIMM], d_fkl[RTOT * DIMM];  // f_k split
__device__ __half d_fvh[RTOT * DIMM], d_fvl[RTOT * DIMM];  // f_v split
__device__ __half d_qch[RTOT * DIMM];                      // q centered, hi only
__device__ __half d_vth[RTOT * DIMM], d_vtl[RTOT * DIMM];  // ikn-scaled v split
__device__ __half d_Mh[HH * QBB * DD * DD], d_Ml[HH * QBB * DD * DD];
__device__ float d_iqn[HH][RTOT];
__device__ float d_ikn[HH][RTOT];
__device__ float d_qr[HH][RTOT];
__device__ float d_kr[HH][RTOT];
__device__ float d_Cpart[HH * GCH][DD * DD];
__device__ float d_cred[HH][16];
__device__ float d_gpart[256][2 * DIMM];
__device__ float d_s1[HH];
__device__ float d_wws[HH];
__device__ float d_gv[HH * QBB][DD];

__device__ __forceinline__ float warpsum(float v) {
#pragma unroll
    for (int o = 16; o; o >>= 1) v += __shfl_xor_sync(0xffffffffu, v, o);
    return v;
}

__device__ __forceinline__ uint32_t smem_u32(const void* p) {
    uint32_t a;
    asm("{ .reg .u64 t; cvta.to.shared.u64 t, %1; cvt.u32.u64 %0, t; }" : "=r"(a) : "l"(p));
    return a;
}
__device__ __forceinline__ uint32_t h2u(__half2 v) { return *reinterpret_cast<uint32_t*>(&v); }

// split fp32 -> fp16 hi (rn) + fp16 lo (rn residual): 22-bit pair
__device__ __forceinline__ void hsplit2(float x0, float x1, uint32_t& h, uint32_t& l) {
    __half2 hh = __floats2half2_rn(x0, x1);
    float2 f = __half22float2(hh);
    __half2 ll = __floats2half2_rn(x0 - f.x, x1 - f.y);
    h = h2u(hh); l = h2u(ll);
}
__device__ __forceinline__ void hsplit4(float x0, float x1, float x2, float x3,
                                        uint2& h, uint2& l) {
    hsplit2(x0, x1, h.x, l.x);
    hsplit2(x2, x3, h.y, l.y);
}

__device__ __forceinline__ void cp16(uint32_t dst, const void* src) {
    asm volatile("cp.async.cg.shared.global [%0], [%1], 16;\n" :: "r"(dst), "l"(src));
}
__device__ __forceinline__ void ldsm_x4(uint32_t* r, uint32_t a) {
    asm volatile("ldmatrix.sync.aligned.m8n8.x4.shared.b16 {%0,%1,%2,%3}, [%4];\n"
                 : "=r"(r[0]), "=r"(r[1]), "=r"(r[2]), "=r"(r[3]) : "r"(a));
}
__device__ __forceinline__ void ldsm_x4_t(uint32_t* r, uint32_t a) {
    asm volatile("ldmatrix.sync.aligned.m8n8.x4.trans.shared.b16 {%0,%1,%2,%3}, [%4];\n"
                 : "=r"(r[0]), "=r"(r[1]), "=r"(r[2]), "=r"(r[3]) : "r"(a));
}
__device__ __forceinline__ void mma_f16(float* d, const uint32_t* a, const uint32_t* b) {
    asm volatile(
        "mma.sync.aligned.m16n8k16.row.col.f32.f16.f16.f32 "
        "{%0,%1,%2,%3}, {%4,%5,%6,%7}, {%8,%9}, {%0,%1,%2,%3};\n"
        : "+f"(d[0]), "+f"(d[1]), "+f"(d[2]), "+f"(d[3])
        : "r"(a[0]), "r"(a[1]), "r"(a[2]), "r"(a[3]), "r"(b[0]), "r"(b[1]));
}

// ---------------- fused: rowstats+LN+split | weight conv ----------------
__global__ void lnwconv_kernel(const float* __restrict__ q, const float* __restrict__ k,
                               const float* __restrict__ v,
                               const float* __restrict__ lng, const float* __restrict__ lnb,
                               const float* __restrict__ w_in, const float* __restrict__ w_out) {
    int idx = blockIdx.x;
    int tid = threadIdx.x;
    if (idx >= 3 * RTOT) {
        int row = idx - 3 * RTOT;   // 0..2047
        const float* src = (row < DIMM) ? w_in + (size_t)row * DIMM
                                        : w_out + (size_t)(row - DIMM) * DIMM;
        __half* H = (row < DIMM) ? d_wih + (size_t)row * DIMM
                                 : d_woh + (size_t)(row - DIMM) * DIMM;
        float4 x = ((const float4*)src)[tid];
        uint2 hv;
        hv.x = h2u(__floats2half2_rn(x.x, x.y));
        hv.y = h2u(__floats2half2_rn(x.z, x.w));
        ((uint2*)H)[tid] = hv;
        return;
    }
    int t = idx >> 13;
    int r = idx & (RTOT - 1);
    const float* A = (t == 0) ? q : (t == 1) ? k : v;
    float4 x = ((const float4*)(A + (size_t)r * DIMM))[tid];
    float s = x.x + x.y + x.z + x.w;
    float sq = x.x * x.x + x.y * x.y + x.z * x.z + x.w * x.w;
    __shared__ float sh[16];
    __shared__ float smu, srs;
    s = warpsum(s); sq = warpsum(sq);
    int w = tid >> 5, lane = tid & 31;
    if (lane == 0) { sh[w] = s; sh[8 + w] = sq; }
    __syncthreads();
    if (tid == 0) {
        float S = 0.f, SQ = 0.f;
#pragma unroll
        for (int i = 0; i < 8; i++) { S += sh[i]; SQ += sh[8 + i]; }
        float mu = S * (1.f / DIMM);
        float var = SQ * (1.f / DIMM) - mu * mu;
        smu = mu;
        srs = rsqrtf(var + 1e-5f);
    }
    __syncthreads();
    float mu = smu, rs = srs;
    float4 g = ((const float4*)lng)[tid];
    float4 b = ((const float4*)lnb)[tid];
    float y0 = (x.x - mu) * rs * g.x + b.x;
    float y1 = (x.y - mu) * rs * g.y + b.y;
    float y2 = (x.z - mu) * rs * g.z + b.z;
    float y3 = (x.w - mu) * rs * g.w + b.w;
    uint2 hv, lv;
    hsplit4(y0, y1, y2, y3, hv, lv);
    ((uint2*)(d_xh[t] + (size_t)r * DIMM))[tid] = hv;
    ((uint2*)(d_xl[t] + (size_t)r * DIMM))[tid] = lv;
}

// =====================================================================
//  big GEMM: C[8192x1024] = A @ B^T, fp16x2 (Ah,Al vs Bh).
//  CTA tile 128x256, K-blocks of 64, 3-stage cp.async pipeline.
// =====================================================================
static constexpr int MM_STAGE = 65536;
static constexpr int MM_SMEM = 3 * MM_STAGE;   // 196608

__device__ __forceinline__ void mm_fill(uint32_t sb, int s, int kb,
                                        const char* const* gsrc, int tid) {
    uint32_t st = sb + s * MM_STAGE;
#pragma unroll
    for (int p = 0; p < 2; p++) {       // A hi/lo: 128 rows x 128B
        uint32_t base = st + p * 16384;
        const char* src = gsrc[p] + kb * 128;
#pragma unroll
        for (int i = 0; i < 4; i++) {
            int id = tid + i * 256;
            int row = id >> 3, c = id & 7;
            uint32_t sw = (uint32_t)((c ^ (row & 7)) << 4);
            cp16(base + row * 128 + sw, src + (size_t)row * 2048 + c * 16);
        }
    }
    {                                    // B hi: 256 rows x 128B
        uint32_t base = st + 32768;
        const char* src = gsrc[2] + kb * 128;
#pragma unroll
        for (int i = 0; i < 8; i++) {
            int id = tid + i * 256;
            int row = id >> 3, c = id & 7;
            uint32_t sw = (uint32_t)((c ^ (row & 7)) << 4);
            cp16(base + row * 128 + sw, src + (size_t)row * 2048 + c * 16);
        }
    }
    asm volatile("cp.async.commit_group;\n");
}

__device__ __forceinline__ void mm_compute(uint32_t st, float acc[4][8][4],
                                           int wm, int wn, int lane) {
    uint32_t bAh = st, bAl = st + 16384, bBh = st + 32768;
    int la7 = lane & 7;
#pragma unroll
    for (int kc = 0; kc < 4; kc++) {
        uint32_t ah[4][4], al[4][4];
        int chA = kc * 2 + (lane >> 4);
#pragma unroll
        for (int mi = 0; mi < 4; mi++) {
            int row = wm * 64 + mi * 16 + la7 + ((lane >> 3) & 1) * 8;
            uint32_t off = (uint32_t)row * 128 + (uint32_t)((chA ^ (row & 7)) << 4);
            ldsm_x4(ah[mi], bAh + off);
            ldsm_x4(al[mi], bAl + off);
        }
        int chB = kc * 2 + ((lane >> 3) & 1);
#pragma unroll
        for (int nhf = 0; nhf < 2; nhf++) {
            uint32_t bh[2][4];
#pragma unroll
            for (int nh = 0; nh < 2; nh++) {
                int row = wn * 64 + (nhf * 2 + nh) * 16 + la7 + (lane >> 4) * 8;
                uint32_t off = (uint32_t)row * 128 + (uint32_t)((chB ^ (row & 7)) << 4);
                ldsm_x4(bh[nh], bBh + off);
            }
#pragma unroll
            for (int mi = 0; mi < 4; mi++)
#pragma unroll
                for (int nj = 0; nj < 4; nj++)
                    mma_f16(acc[mi][nhf * 4 + nj], ah[mi], &bh[nj >> 1][2 * (nj & 1)]);
#pragma unroll
            for (int mi = 0; mi < 4; mi++)
#pragma unroll
                for (int nj = 0; nj < 4; nj++)
                    mma_f16(acc[mi][nhf * 4 + nj], al[mi], &bh[nj >> 1][2 * (nj & 1)]);
        }
    }
}

template <bool OUTF32>
__device__ __forceinline__ void mm_body(
    const __half* __restrict__ Ah, const __half* __restrict__ Al,
    const __half* __restrict__ Bh,
    float* __restrict__ C, const float* __restrict__ bias,
    __half* __restrict__ SH, __half* __restrict__ SL) {
    extern __shared__ char smem[];
    int tid = threadIdx.x, lane = tid & 31, wid = tid >> 5;
    int wm = wid >> 2, wn = wid & 3;
    int m0 = blockIdx.y * 128, n0 = blockIdx.x * 256;
    uint32_t sb = smem_u32(smem);

    const char* gsrc[3];
    gsrc[0] = (const char*)(Ah + (size_t)m0 * DIMM);
    gsrc[1] = (const char*)(Al + (size_t)m0 * DIMM);
    gsrc[2] = (const char*)(Bh + (size_t)n0 * DIMM);

    float acc[4][8][4];
#pragma unroll
    for (int i = 0; i < 4; i++)
#pragma unroll
        for (int j = 0; j < 8; j++)
#pragma unroll
            for (int q = 0; q < 4; q++) acc[i][j][q] = 0.f;

    mm_fill(sb, 0, 0, gsrc, tid);
    mm_fill(sb, 1, 1, gsrc, tid);

    for (int kb = 0; kb < 16; kb++) {
        if (kb < 15) asm volatile("cp.async.wait_group 1;\n");
        else         asm volatile("cp.async.wait_group 0;\n");
        __syncthreads();
        if (kb + 2 < 16) mm_fill(sb, (kb + 2) % 3, kb + 2, gsrc, tid);
        mm_compute(sb + (kb % 3) * MM_STAGE, acc, wm, wn, lane);
    }

#pragma unroll
    for (int mi = 0; mi < 4; mi++) {
        int r0 = m0 + wm * 64 + mi * 16 + (lane >> 2);
#pragma unroll
        for (int ni = 0; ni < 8; ni++) {
            int c = n0 + wn * 64 + ni * 8 + (lane & 3) * 2;
            float2 v0 = make_float2(acc[mi][ni][0], acc[mi][ni][1]);
            float2 v1 = make_float2(acc[mi][ni][2], acc[mi][ni][3]);
            if (OUTF32) {
                float b0 = bias[c], b1 = bias[c + 1];
                v0.x += b0; v0.y += b1;
                v1.x += b0; v1.y += b1;
                *(float2*)(C + (size_t)r0 * DIMM + c) = v0;
                *(float2*)(C + (size_t)(r0 + 8) * DIMM + c) = v1;
            } else {
                uint32_t hh, ll;
                hsplit2(v0.x, v0.y, hh, ll);
                *(uint32_t*)(SH + (size_t)r0 * DIMM + c) = hh;
                *(uint32_t*)(SL + (size_t)r0 * DIMM + c) = ll;
                hsplit2(v1.x, v1.y, hh, ll);
                *(uint32_t*)(SH + (size_t)(r0 + 8) * DIMM + c) = hh;
                *(uint32_t*)(SL + (size_t)(r0 + 8) * DIMM + c) = ll;
            }
        }
    }
}

__global__ void __launch_bounds__(256, 1) mm_proj_kernel() {
    int which = blockIdx.z;
    if (which == 0)
        mm_body<false>(d_xh[0], d_xl[0], d_wih, nullptr, nullptr, d_fqh, d_fql);
    else if (which == 1)
        mm_body<false>(d_xh[1], d_xl[1], d_wih, nullptr, nullptr, d_fkh, d_fkl);
    else
        mm_body<false>(d_xh[2], d_xl[2], d_wih, nullptr, nullptr, d_fvh, d_fvl);
}

__global__ void __launch_bounds__(256, 1) mm_out_kernel(const float* __restrict__ bias,
                                                        float* __restrict__ out) {
    mm_body<true>(d_oh, d_ol, d_woh, out, bias, nullptr, nullptr);
}

// =====================================================================
//  merged per-(head,row) stats (hi-only) + centered-q hi + ikn-scaled v split
// =====================================================================
__global__ void statsprep_kernel() {
    int r = blockIdx.x;
    int tid = threadIdx.x;
    int w = tid >> 5, lane = tid & 31;
    size_t base = (size_t)r * DIMM + w * DD + lane * 4;

    // f_q: stats from hi + centered hi
    {
        uint2 uh = *(const uint2*)(d_fqh + base);
        float2 a0 = __half22float2(*(__half2*)&uh.x), a1 = __half22float2(*(__half2*)&uh.y);
        float x0 = a0.x, x1 = a0.y, x2 = a1.x, x3 = a1.y;
        float s = warpsum(x0 + x1 + x2 + x3);
        float sq = warpsum(x0 * x0 + x1 * x1 + x2 * x2 + x3 * x3);
        float mean = s * (1.f / DD);
        float var = (sq - s * s * (1.f / DD)) * (1.f / (DD - 1));
        if (lane == 0) {
            d_iqn[w][r] = rsqrtf(sq);
            d_qr[w][r] = 2.f * fminf(var, 1.f) / (var + 1.f);
        }
        uint2 hv;
        hv.x = h2u(__floats2half2_rn(x0 - mean, x1 - mean));
        hv.y = h2u(__floats2half2_rn(x2 - mean, x3 - mean));
        *(uint2*)(d_qch + base) = hv;
    }
    // f_k: stats from hi (ikn broadcast to all lanes)
    float ikn;
    {
        uint2 uh = *(const uint2*)(d_fkh + base);
        float2 a0 = __half22float2(*(__half2*)&uh.x), a1 = __half22float2(*(__half2*)&uh.y);
        float k0 = a0.x, k1 = a0.y, k2 = a1.x, k3 = a1.y;
        float s = warpsum(k0 + k1 + k2 + k3);
        float sq = warpsum(k0 * k0 + k1 * k1 + k2 * k2 + k3 * k3);
        ikn = rsqrtf(sq);
        float var = (sq - s * s * (1.f / DD)) * (1.f / (DD - 1));
        if (lane == 0) {
            d_ikn[w][r] = ikn;
            d_kr[w][r] = 2.f * fminf(var, 1.f) / (var + 1.f);
        }
    }
    // f_v -> vt = fv * ikn, split hi/lo (full precision source)
    {
        uint2 uh = *(const uint2*)(d_fvh + base);
        uint2 ul = *(const uint2*)(d_fvl + base);
        float2 a0 = __half22float2(*(__half2*)&uh.x), a1 = __half22float2(*(__half2*)&uh.y);
        float2 b0 = __half22float2(*(__half2*)&ul.x), b1 = __half22float2(*(__half2*)&ul.y);
        float v0 = (a0.x + b0.x) * ikn, v1 = (a0.y + b0.y) * ikn;
        float v2 = (a1.x + b1.x) * ikn, v3 = (a1.y + b1.y) * ikn;
        uint2 hv, lv;
        hsplit4(v0, v1, v2, v3, hv, lv);
        *(uint2*)(d_vth + base) = hv;
        *(uint2*)(d_vtl + base) = lv;
    }
}

// =====================================================================
//  mid_kernel bodies: kvm (tc), gram1 (tc), gpart (mem), gv (mem)
//  32-row K-chunks, double-buffered, 2 CTAs/SM.
// =====================================================================
static constexpr int ATB_MAT = 32 * 272;       // 8704
static constexpr int ATB_STG = 4 * ATB_MAT;    // 34816
static constexpr int MID_SMEM = 2 * ATB_STG;   // 69632

__device__ __forceinline__ void atb_fill(uint32_t sb, int s, int c,
        const __half* Ah, const __half* Al,
        const __half* Bh, const __half* Bl) {
    int tid = threadIdx.x;
    const __half* srcs[4] = {Ah, Al, Bh, Bl};
#pragma unroll
    for (int p = 0; p < 4; p++) {
        uint32_t base = sb + s * ATB_STG + p * ATB_MAT;
        const __half* src = srcs[p];
#pragma unroll
        for (int i = 0; i < 2; i++) {
            int id = tid + i * 256;
            int row = id >> 4, c16 = id & 15;
            cp16(base + row * 272 + c16 * 16,
                 src + (size_t)(c * 32 + row) * DIMM + c16 * 8);
        }
    }
    asm volatile("cp.async.commit_group;\n");
}

__device__ __forceinline__ void atb_compute(uint32_t sb, int s, float acc[4][4][4],
                                            int wm, int wn, int lane) {
    uint32_t bA  = sb + s * ATB_STG;
    uint32_t bAl = bA + ATB_MAT;
    uint32_t bB  = bA + 2 * ATB_MAT;
    uint32_t bBl = bA + 3 * ATB_MAT;
    int la7 = lane & 7;
    int arow = ((lane >> 4) << 3) + la7;
    int acol = (((lane >> 3) & 1) << 3);
    int brow = (((lane >> 3) & 1) << 3) + la7;
    int bcol = ((lane >> 4) << 3);
#pragma unroll
    for (int kc = 0; kc < 2; kc++) {
        uint32_t ah[4][4], al[4][4];
#pragma unroll
        for (int mi = 0; mi < 4; mi++) {
            uint32_t off = (uint32_t)(kc * 16 + arow) * 272 +
                           (uint32_t)(wm * 64 + mi * 16 + acol) * 2;
            ldsm_x4_t(ah[mi], bA + off);
            ldsm_x4_t(al[mi], bAl + off);
        }
        uint32_t bh[4][2], bl[4][2];
#pragma unroll
        for (int nh = 0; nh < 2; nh++) {
            uint32_t off = (uint32_t)(kc * 16 + brow) * 272 +
                           (uint32_t)(wn * 32 + nh * 16 + bcol) * 2;
            uint32_t r[4];
            ldsm_x4_t(r, bB + off);
            bh[2 * nh][0] = r[0]; bh[2 * nh][1] = r[1];
            bh[2 * nh + 1][0] = r[2]; bh[2 * nh + 1][1] = r[3];
            ldsm_x4_t(r, bBl + off);
            bl[2 * nh][0] = r[0]; bl[2 * nh][1] = r[1];
            bl[2 * nh + 1][0] = r[2]; bl[2 * nh + 1][1] = r[3];
        }
#pragma unroll
        for (int mi = 0; mi < 4; mi++)
#pragma unroll
            for (int ni = 0; ni < 4; ni++) mma_f16(acc[mi][ni], ah[mi], bh[ni]);
#pragma unroll
        for (int mi = 0; mi < 4; mi++)
#pragma unroll
            for (int ni = 0; ni < 4; ni++) mma_f16(acc[mi][ni], al[mi], bh[ni]);
#pragma unroll
        for (int mi = 0; mi < 4; mi++)
#pragma unroll
            for (int ni = 0; ni < 4; ni++) mma_f16(acc[mi][ni], ah[mi], bl[ni]);
    }
}

__device__ void kvm_body(char* smem, int blk) {
    int h = blk >> 4, qi = blk & 15;
    size_t off = (size_t)(qi * NN) * DIMM + h * DD;
    uint32_t sb = smem_u32(smem);
    int tid = threadIdx.x, lane = tid & 31, wid = tid >> 5;
    int wm = wid >> 2, wn = wid & 3;
    float acc[4][4][4];
#pragma unroll
    for (int i = 0; i < 4; i++)
#pragma unroll
        for (int j = 0; j < 4; j++)
#pragma unroll
            for (int q = 0; q < 4; q++) acc[i][j][q] = 0.f;

    atb_fill(sb, 0, 0, d_fkh + off, d_fkl + off, d_vth + off, d_vtl + off);
    for (int c = 0; c < 16; c++) {
        asm volatile("cp.async.wait_group 0;\n");
        __syncthreads();
        if (c + 1 < 16)
            atb_fill(sb, (c + 1) & 1, c + 1, d_fkh + off, d_fkl + off, d_vth + off, d_vtl + off);
        atb_compute(sb, c & 1, acc, wm, wn, lane);
    }
    __half* Oh = d_Mh + (size_t)blk * DD * DD;
    __half* Ol = d_Ml + (size_t)blk * DD * DD;
#pragma unroll
    for (int mi = 0; mi < 4; mi++) {
        int d0 = wm * 64 + mi * 16 + (lane >> 2);
#pragma unroll
        for (int ni = 0; ni < 4; ni++) {
            int e = wn * 32 + ni * 8 + (lane & 3) * 2;
            uint32_t hh, ll;
            hsplit2(acc[mi][ni][0], acc[mi][ni][1], hh, ll);
            *(uint32_t*)(Oh + d0 * DD + e) = hh;
            *(uint32_t*)(Ol + d0 * DD + e) = ll;
            hsplit2(acc[mi][ni][2], acc[mi][ni][3], hh, ll);
            *(uint32_t*)(Oh + (d0 + 8) * DD + e) = hh;
            *(uint32_t*)(Ol + (d0 + 8) * DD + e) = ll;
        }
    }
}

__device__ void gram1_body(char* smem, int ch, int h) {
    const __half* A = d_qch + (size_t)(ch * 512) * DIMM + h * DD;
    uint32_t sb = smem_u32(smem);
    int tid = threadIdx.x, lane = tid & 31, wid = tid >> 5;
    int wm = wid >> 2, wn = wid & 3;
    int la7 = lane & 7;
    float acc[4][4][4];
#pragma unroll
    for (int i = 0; i < 4; i++)
#pragma unroll
        for (int j = 0; j < 4; j++)
#pragma unroll
            for (int q = 0; q < 4; q++) acc[i][j][q] = 0.f;

    auto fill = [&](int s, int c) {
#pragma unroll
        for (int i = 0; i < 2; i++) {
            int id = tid + i * 256;
            int row = id >> 4, c16 = id & 15;
            cp16(sb + s * ATB_MAT + row * 272 + c16 * 16,
                 A + (size_t)(c * 32 + row) * DIMM + c16 * 8);
        }
        asm volatile("cp.async.commit_group;\n");
    };

    fill(0, 0);
    int arow = ((lane >> 4) << 3) + la7;
    int acol = (((lane >> 3) & 1) << 3);
    int brow = (((lane >> 3) & 1) << 3) + la7;
    int bcol = ((lane >> 4) << 3);
    for (int c = 0; c < 16; c++) {
        asm volatile("cp.async.wait_group 0;\n");
        __syncthreads();
        if (c + 1 < 16) fill((c + 1) & 1, c + 1);
        uint32_t bA = sb + (c & 1) * ATB_MAT;
#pragma unroll
        for (int kc = 0; kc < 2; kc++) {
            uint32_t ah[4][4];
#pragma unroll
            for (int mi = 0; mi < 4; mi++) {
                uint32_t off = (uint32_t)(kc * 16 + arow) * 272 +
                               (uint32_t)(wm * 64 + mi * 16 + acol) * 2;
                ldsm_x4_t(ah[mi], bA + off);
            }
            uint32_t bh[4][2];
#pragma unroll
            for (int nh = 0; nh < 2; nh++) {
                uint32_t off = (uint32_t)(kc * 16 + brow) * 272 +
                               (uint32_t)(wn * 32 + nh * 16 + bcol) * 2;
                uint32_t r[4];
                ldsm_x4_t(r, bA + off);
                bh[2 * nh][0] = r[0]; bh[2 * nh][1] = r[1];
                bh[2 * nh + 1][0] = r[2]; bh[2 * nh + 1][1] = r[3];
            }
#pragma unroll
            for (int mi = 0; mi < 4; mi++)
#pragma unroll
                for (int ni = 0; ni < 4; ni++) mma_f16(acc[mi][ni], ah[mi], bh[ni]);
        }
    }
    float* Cf = d_Cpart[h * GCH + ch];
#pragma unroll
    for (int mi = 0; mi < 4; mi++) {
        int d0 = wm * 64 + mi * 16 + (lane >> 2);
#pragma unroll
        for (int ni = 0; ni < 4; ni++) {
            int e = wn * 32 + ni * 8 + (lane & 3) * 2;
            *(float2*)(Cf + d0 * DD + e) = make_float2(acc[mi][ni][0], acc[mi][ni][1]);
            *(float2*)(Cf + (d0 + 8) * DD + e) = make_float2(acc[mi][ni][2], acc[mi][ni][3]);
        }
    }
}

__device__ void gpart_body(int b) {
    int r0 = b * 32;
    int t = threadIdx.x;
    float2 sq0 = {0.f, 0.f}, sq1 = {0.f, 0.f};
    float2 sk0 = {0.f, 0.f}, sk1 = {0.f, 0.f};
    for (int row = 0; row < 32; row++) {
        const __half2* fq = (const __half2*)(d_fqh + (size_t)(r0 + row) * DIMM);
        const __half2* fk = (const __half2*)(d_fkh + (size_t)(r0 + row) * DIMM);
        float2 a = __half22float2(fq[t]);       sq0.x += a.x; sq0.y += a.y;
        float2 c = __half22float2(fq[t + 256]); sq1.x += c.x; sq1.y += c.y;
        float2 e = __half22float2(fk[t]);       sk0.x += e.x; sk0.y += e.y;
        float2 f = __half22float2(fk[t + 256]); sk1.x += f.x; sk1.y += f.y;
    }
    d_gpart[b][2 * t] = sq0.x;       d_gpart[b][2 * t + 1] = sq0.y;
    d_gpart[b][512 + 2 * t] = sq1.x; d_gpart[b][512 + 2 * t + 1] = sq1.y;
    d_gpart[b][DIMM + 2 * t] = sk0.x;       d_gpart[b][DIMM + 2 * t + 1] = sk0.y;
    d_gpart[b][DIMM + 512 + 2 * t] = sk1.x; d_gpart[b][DIMM + 512 + 2 * t + 1] = sk1.y;
}

__device__ void gv_body(int blk) {
    int h = blk >> 4, qi = blk & 15;
    int r0 = qi * NN;
    int tid = threadIdx.x;
    int e = tid & 127, half = tid >> 7;
    __shared__ float kr[NN];
    __shared__ float part[2][DD];
    for (int i = tid; i < NN; i += 256) kr[i] = d_kr[h][r0 + i];
    __syncthreads();
    float a0 = 0.f, a1 = 0.f;
    int nb = half * 256;
    const __half* vh = d_fvh + (size_t)(r0 + nb) * DIMM + h * DD + e;
    const __half* vl = d_fvl + (size_t)(r0 + nb) * DIMM + h * DD + e;
#pragma unroll 2
    for (int n = 0; n < 256; n += 2) {
        a0 += kr[nb + n] * (__half2float(vh[(size_t)n * DIMM]) + __half2float(vl[(size_t)n * DIMM]));
        a1 += kr[nb + n + 1] * (__half2float(vh[(size_t)(n + 1) * DIMM]) + __half2float(vl[(size_t)(n + 1) * DIMM]));
    }
    part[half][e] = a0 + a1;
    __syncthreads();
    if (half == 0) d_gv[blk][e] = part[0][e] + part[1][e];
}

// mid_kernel: 0..127 kvm | 128..255 gram1 | 256..511 gpart | 512..639 gv
__global__ void __launch_bounds__(256, 2) mid_kernel() {
    extern __shared__ char smem[];
    int b = blockIdx.x;
    if (b < 128) kvm_body(smem, b);
    else if (b < 256) { int i = b - 128; gram1_body(smem, i & 15, i >> 4); }
    else if (b < 512) gpart_body(b - 256);
    else gv_body(b - 512);
}

// ---------------- creduce1: gram partial reduce ----------------
__global__ void creduce1_kernel() {
    int ch = blockIdx.x;
    int h = blockIdx.y;
    int tid = threadIdx.x;
    float ssum = 0.f;
#pragma unroll
    for (int u = 0; u < 4; u++) {
        int i = ch * 1024 + tid + u * 256;
        float c = 0.f;
#pragma unroll
        for (int p = 0; p < GCH; p++) c += d_Cpart[h * GCH + p][i];
        if ((i / DD) != (i % DD)) ssum += c * c;
    }
    __shared__ float sh[8];
    ssum = warpsum(ssum);
    int w = tid >> 5, lane = tid & 31;
    if (lane == 0) sh[w] = ssum;
    __syncthreads();
    if (tid == 0) {
        float S = 0.f;
#pragma unroll
        for (int i = 0; i < 8; i++) S += sh[i];
        d_cred[h][ch] = S;
    }
}

// ---------------- weight-predictor MLP (+ inline creduce2) ----------------
__global__ void wp_kernel(const float* __restrict__ w1, const float* __restrict__ b1,
                          const float* __restrict__ lng, const float* __restrict__ lnb,
                          const float* __restrict__ w2, const float* __restrict__ b2) {
    __shared__ float qg[DIMM], kg[DIMM];
    __shared__ float h1[HH][DD];
    __shared__ float logits[HH][3];
    __shared__ float sdsc[HH];
    int tid = threadIdx.x;
    if (tid < 8) {
        float S = 0.f;
#pragma unroll
        for (int i = 0; i < 16; i++) S += d_cred[tid][i];
        float fro = sqrtf(S) * (1.f / RTOT);
        float score = fro * (1.f / (128.f * 128.f));
        sdsc[tid] = expf(-5.f * score);
    }
    for (int i = tid; i < DIMM; i += 256) {
        float s = 0.f, s2 = 0.f;
        for (int b = 0; b < 256; b++) { s += d_gpart[b][i]; s2 += d_gpart[b][DIMM + i]; }
        qg[i] = s * (1.f / RTOT);
        kg[i] = s2 * (1.f / RTOT);
    }
    __syncthreads();
    for (int idx = tid; idx < HH * DD; idx += 256) {
        int h = idx / DD, i = idx % DD;
        float s = b1[i];
        const float* wr = w1 + i * 256;
#pragma unroll 4
        for (int j = 0; j < 128; j++) s += qg[h * 128 + j] * wr[j];
#pragma unroll 4
        for (int j = 0; j < 128; j++) s += kg[h * 128 + j] * wr[128 + j];
        h1[h][i] = s;
    }
    __syncthreads();
    int w = tid >> 5, lane = tid & 31;
    if (w < 8) {
        float s = 0.f, sq = 0.f;
        for (int i = lane; i < DD; i += 32) { float v = h1[w][i]; s += v; sq += v * v; }
        s = warpsum(s); sq = warpsum(sq);
        float mean = s * (1.f / DD);
        float var = sq * (1.f / DD) - mean * mean;
        float rs = rsqrtf(var + 1e-5f);
        for (int i = lane; i < DD; i += 32) {
            float vv = (h1[w][i] - mean) * rs * lng[i] + lnb[i];
            h1[w][i] = fmaxf(vv, 0.f);
        }
    }
    __syncthreads();
    if (tid < 24) {
        int h = tid / 3, c = tid % 3;
        float s = b2[c];
        const float* wr = w2 + c * DD;
        for (int i = 0; i < DD; i++) s += h1[h][i] * wr[i];
        logits[h][c] = s;
    }
    __syncthreads();
    if (tid < 8) {
        float a = logits[tid][0], b = logits[tid][1], c = logits[tid][2];
        float m = fmaxf(a, fmaxf(b, c));
        float ea = expf(a - m), eb = expf(b - m), ec = expf(c - m);
        float inv = 1.f / (ea + eb + ec);
        d_s1[tid] = ea * inv + eb * inv * sdsc[tid];
        d_wws[tid] = ec * inv;
    }
}

// =====================================================================
//  attout: att[128x128] = f_q @ M (3-term), + rank-1 term -> oh/ol
// =====================================================================
static constexpr int AO_MAT = 128 * 272;       // 34816
static constexpr int AO_SMEM = 4 * AO_MAT;     // 139264

__global__ void __launch_bounds__(256, 1) attout_tc_kernel() {
    int blk = blockIdx.y, mt = blockIdx.x;
    int h = blk >> 4, qi = blk & 15;
    int r0g = qi * NN + mt * 128;
    int co = h * DD;
    extern __shared__ char smem[];
    uint32_t sb = smem_u32(smem);
    int tid = threadIdx.x, lane = tid & 31, wid = tid >> 5;
    int wm = wid >> 2, wn = wid & 3;
    int la7 = lane & 7;

    {
        const __half* Asrc[2] = {d_fqh, d_fql};
#pragma unroll
        for (int p = 0; p < 2; p++) {
            uint32_t base = sb + p * AO_MAT;
            const __half* src = Asrc[p] + (size_t)r0g * DIMM + co;
#pragma unroll
            for (int i = 0; i < 8; i++) {
                int id = tid + i * 256;
                int row = id >> 4, c16 = id & 15;
                cp16(base + row * 272 + c16 * 16, src + (size_t)row * DIMM + c16 * 8);
            }
        }
        const __half* Bsrc[2] = {d_Mh + (size_t)blk * DD * DD,
                                 d_Ml + (size_t)blk * DD * DD};
#pragma unroll
        for (int p = 0; p < 2; p++) {
            uint32_t base = sb + (2 + p) * AO_MAT;
            const __half* src = Bsrc[p];
#pragma unroll
            for (int i = 0; i < 8; i++) {
                int id = tid + i * 256;
                int row = id >> 4, c16 = id & 15;
                cp16(base + row * 272 + c16 * 16, src + row * DD + c16 * 8);
            }
        }
        asm volatile("cp.async.commit_group;\ncp.async.wait_group 0;\n");
        __syncthreads();
    }

    float acc[4][4][4];
#pragma unroll
    for (int i = 0; i < 4; i++)
#pragma unroll
        for (int j = 0; j < 4; j++)
#pragma unroll
            for (int q = 0; q < 4; q++) acc[i][j][q] = 0.f;

    uint32_t bA  = sb;
    uint32_t bAl = sb + AO_MAT;
    uint32_t bB  = sb + 2 * AO_MAT;
    uint32_t bBl = sb + 3 * AO_MAT;
    int brow = (((lane >> 3) & 1) << 3) + la7;
    int bcol = ((lane >> 4) << 3);
#pragma unroll
    for (int kc = 0; kc < 8; kc++) {
        uint32_t ah[4][4], al[4][4];
#pragma unroll
        for (int mi = 0; mi < 4; mi++) {
            uint32_t off = (uint32_t)(wm * 64 + mi * 16 + (lane & 15)) * 272 +
                           (uint32_t)(kc * 16 + ((lane >> 4) << 3)) * 2;
            ldsm_x4(ah[mi], bA + off);
            ldsm_x4(al[mi], bAl + off);
        }
        uint32_t bh[4][2], bl[4][2];
#pragma unroll
        for (int nh = 0; nh < 2; nh++) {
            uint32_t off = (uint32_t)(kc * 16 + brow) * 272 +
                           (uint32_t)(wn * 32 + nh * 16 + bcol) * 2;
            uint32_t r[4];
            ldsm_x4_t(r, bB + off);
            bh[2 * nh][0] = r[0]; bh[2 * nh][1] = r[1];
            bh[2 * nh + 1][0] = r[2]; bh[2 * nh + 1][1] = r[3];
            ldsm_x4_t(r, bBl + off);
            bl[2 * nh][0] = r[0]; bl[2 * nh][1] = r[1];
            bl[2 * nh + 1][0] = r[2]; bl[2 * nh + 1][1] = r[3];
        }
#pragma unroll
        for (int mi = 0; mi < 4; mi++)
#pragma unroll
            for (int ni = 0; ni < 4; ni++) mma_f16(acc[mi][ni], ah[mi], bh[ni]);
#pragma unroll
        for (int mi = 0; mi < 4; mi++)
#pragma unroll
            for (int ni = 0; ni < 4; ni++) mma_f16(acc[mi][ni], al[mi], bh[ni]);
#pragma unroll
        for (int mi = 0; mi < 4; mi++)
#pragma unroll
            for (int ni = 0; ni < 4; ni++) mma_f16(acc[mi][ni], ah[mi], bl[ni]);
    }

    float s1 = d_s1[h], ww = d_wws[h];
#pragma unroll
    for (int mi = 0; mi < 4; mi++) {
        int rA = r0g + wm * 64 + mi * 16 + (lane >> 2);
        int rB = rA + 8;
        float f1a = s1 * d_iqn[h][rA], f2a = ww * d_qr[h][rA];
        float f1b = s1 * d_iqn[h][rB], f2b = ww * d_qr[h][rB];
#pragma unroll
        for (int ni = 0; ni < 4; ni++) {
            int c = wn * 32 + ni * 8 + (lane & 3) * 2;
            float g0 = d_gv[blk][c], g1 = d_gv[blk][c + 1];
            float o0 = f1a * acc[mi][ni][0] + f2a * g0;
            float o1 = f1a * acc[mi][ni][1] + f2a * g1;
            float o2 = f1b * acc[mi][ni][2] + f2b * g0;
            float o3 = f1b * acc[mi][ni][3] + f2b * g1;
            uint32_t hh, ll;
            hsplit2(o0, o1, hh, ll);
            *(uint32_t*)(d_oh + (size_t)rA * DIMM + co + c) = hh;
            *(uint32_t*)(d_ol + (size_t)rA * DIMM + co + c) = ll;
            hsplit2(o2, o3, hh, ll);
            *(uint32_t*)(d_oh + (size_t)rB * DIMM + co + c) = hh;
            *(uint32_t*)(d_ol + (size_t)rB * DIMM + co + c) = ll;
        }
    }
}

// ---------------- launch ----------------
extern "C" void kernel_launch(void* const* d_in, const int* in_sizes, int n_in,
                              void* d_out, int out_size) {
    const float* q      = (const float*)d_in[0];
    const float* k      = (const float*)d_in[1];
    const float* v      = (const float*)d_in[2];
    const float* ln_g   = (const float*)d_in[3];
    const float* ln_b   = (const float*)d_in[4];
    const float* w_in   = (const float*)d_in[5];
    const float* wp_w1  = (const float*)d_in[6];
    const float* wp_b1  = (const float*)d_in[7];
    const float* wp_lng = (const float*)d_in[8];
    const float* wp_lnb = (const float*)d_in[9];
    const float* wp_w2  = (const float*)d_in[10];
    const float* wp_b2  = (const float*)d_in[11];
    const float* w_out  = (const float*)d_in[12];
    const float* b_out  = (const float*)d_in[13];
    float* out = (float*)d_out;

    cudaFuncSetAttribute(mm_proj_kernel, cudaFuncAttributeMaxDynamicSharedMemorySize, MM_SMEM);
    cudaFuncSetAttribute(mm_out_kernel, cudaFuncAttributeMaxDynamicSharedMemorySize, MM_SMEM);
    cudaFuncSetAttribute(mid_kernel, cudaFuncAttributeMaxDynamicSharedMemorySize, MID_SMEM);
    cudaFuncSetAttribute(attout_tc_kernel, cudaFuncAttributeMaxDynamicSharedMemorySize, AO_SMEM);

    lnwconv_kernel<<<3 * RTOT + 2 * DIMM, 256>>>(q, k, v, ln_g, ln_b, w_in, w_out);

    dim3 gproj(DIMM / 256, RTOT / 128, 3);   // (4, 64, 3)
    mm_proj_kernel<<<gproj, 256, MM_SMEM>>>();

    statsprep_kernel<<<RTOT, 256>>>();

    mid_kernel<<<640, 256, MID_SMEM>>>();

    dim3 gcr1(16, HH);
    creduce1_kernel<<<gcr1, 256>>>();
    wp_kernel<<<1, 256>>>(wp_w1, wp_b1, wp_lng, wp_lnb, wp_w2, wp_b2);

    dim3 gatt(4, HH * QBB);
    attout_tc_kernel<<<gatt, 256, AO_SMEM>>>();

    dim3 gout(DIMM / 256, RTOT / 128);       // (4, 64)
    mm_out_kernel<<<gout, 256, MM_SMEM>>>(b_out, out);
}

// round 17
// speedup vs baseline: 1.0295x; 1.0295x over previous
#include <cuda_runtime.h>
#include <cuda_fp16.h>
#include <math.h>
#include <stdint.h>

// Problem constants
#define RTOT 8192     // QB*N tokens
#define DIMM 1024
#define HH 8
#define DD 128
#define NN 512
#define QBB 16
#define GCH 16        // gram split-K chunks (512 rows each)

// ---------------- static device scratch (no runtime allocation) ----------------
__device__ __half d_xh[3][RTOT * DIMM];   // LN(x) hi fp16 (q,k,v)
__device__ __half d_xl[3][RTOT * DIMM];   // LN(x) lo residual
__device__ __half d_oh[RTOT * DIMM];      // att output hi
__device__ __half d_ol[RTOT * DIMM];      // att output lo
__device__ __half d_wih[DIMM * DIMM];     // w_in hi (2-term GEMM)
__device__ __half d_woh[DIMM * DIMM];     // w_out hi (2-term GEMM)
__device__ __half d_fqh[RTOT * DIMM], d_fql[RTOT * DIMM];  // f_q split
__device__ __half d_fkh[RTOT * DIMM], d_fkl[RTOT * DIMM];  // f_k split
__device__ __half d_fvh[RTOT * DIMM], d_fvl[RTOT * DIMM];  // f_v split
__device__ __half d_qch[RTOT * DIMM];                      // q centered, hi only
__device__ __half d_vth[RTOT * DIMM];                      // ikn-scaled v, hi only
__device__ __half d_Mh[HH * QBB * DD * DD];                // M hi only
__device__ float d_iqn[HH][RTOT];
__device__ float d_ikn[HH][RTOT];
__device__ float d_qr[HH][RTOT];
__device__ float d_kr[HH][RTOT];
__device__ float d_Cpart[HH * GCH][DD * DD];
__device__ float d_cred[HH][16];
__device__ float d_gpart[256][2 * DIMM];
__device__ float d_s1[HH];
__device__ float d_wws[HH];
__device__ float d_gv[HH * QBB][DD];

__device__ __forceinline__ float warpsum(float v) {
#pragma unroll
    for (int o = 16; o; o >>= 1) v += __shfl_xor_sync(0xffffffffu, v, o);
    return v;
}

__device__ __forceinline__ uint32_t smem_u32(const void* p) {
    uint32_t a;
    asm("{ .reg .u64 t; cvta.to.shared.u64 t, %1; cvt.u32.u64 %0, t; }" : "=r"(a) : "l"(p));
    return a;
}
__device__ __forceinline__ uint32_t h2u(__half2 v) { return *reinterpret_cast<uint32_t*>(&v); }

// split fp32 -> fp16 hi (rn) + fp16 lo (rn residual): 22-bit pair
__device__ __forceinline__ void hsplit2(float x0, float x1, uint32_t& h, uint32_t& l) {
    __half2 hh = __floats2half2_rn(x0, x1);
    float2 f = __half22float2(hh);
    __half2 ll = __floats2half2_rn(x0 - f.x, x1 - f.y);
    h = h2u(hh); l = h2u(ll);
}
__device__ __forceinline__ void hsplit4(float x0, float x1, float x2, float x3,
                                        uint2& h, uint2& l) {
    hsplit2(x0, x1, h.x, l.x);
    hsplit2(x2, x3, h.y, l.y);
}

__device__ __forceinline__ void cp16(uint32_t dst, const void* src) {
    asm volatile("cp.async.cg.shared.global [%0], [%1], 16;\n" :: "r"(dst), "l"(src));
}
__device__ __forceinline__ void ldsm_x4(uint32_t* r, uint32_t a) {
    asm volatile("ldmatrix.sync.aligned.m8n8.x4.shared.b16 {%0,%1,%2,%3}, [%4];\n"
                 : "=r"(r[0]), "=r"(r[1]), "=r"(r[2]), "=r"(r[3]) : "r"(a));
}
__device__ __forceinline__ void ldsm_x4_t(uint32_t* r, uint32_t a) {
    asm volatile("ldmatrix.sync.aligned.m8n8.x4.trans.shared.b16 {%0,%1,%2,%3}, [%4];\n"
                 : "=r"(r[0]), "=r"(r[1]), "=r"(r[2]), "=r"(r[3]) : "r"(a));
}
__device__ __forceinline__ void mma_f16(float* d, const uint32_t* a, const uint32_t* b) {
    asm volatile(
        "mma.sync.aligned.m16n8k16.row.col.f32.f16.f16.f32 "
        "{%0,%1,%2,%3}, {%4,%5,%6,%7}, {%8,%9}, {%0,%1,%2,%3};\n"
        : "+f"(d[0]), "+f"(d[1]), "+f"(d[2]), "+f"(d[3])
        : "r"(a[0]), "r"(a[1]), "r"(a[2]), "r"(a[3]), "r"(b[0]), "r"(b[1]));
}

// ---------------- fused: rowstats+LN+split | weight conv ----------------
__global__ void lnwconv_kernel(const float* __restrict__ q, const float* __restrict__ k,
                               const float* __restrict__ v,
                               const float* __restrict__ lng, const float* __restrict__ lnb,
                               const float* __restrict__ w_in, const float* __restrict__ w_out) {
    int idx = blockIdx.x;
    int tid = threadIdx.x;
    if (idx >= 3 * RTOT) {
        int row = idx - 3 * RTOT;   // 0..2047
        const float* src = (row < DIMM) ? w_in + (size_t)row * DIMM
                                        : w_out + (size_t)(row - DIMM) * DIMM;
        __half* H = (row < DIMM) ? d_wih + (size_t)row * DIMM
                                 : d_woh + (size_t)(row - DIMM) * DIMM;
        float4 x = ((const float4*)src)[tid];
        uint2 hv;
        hv.x = h2u(__floats2half2_rn(x.x, x.y));
        hv.y = h2u(__floats2half2_rn(x.z, x.w));
        ((uint2*)H)[tid] = hv;
        return;
    }
    int t = idx >> 13;
    int r = idx & (RTOT - 1);
    const float* A = (t == 0) ? q : (t == 1) ? k : v;
    float4 x = ((const float4*)(A + (size_t)r * DIMM))[tid];
    float s = x.x + x.y + x.z + x.w;
    float sq = x.x * x.x + x.y * x.y + x.z * x.z + x.w * x.w;
    __shared__ float sh[16];
    __shared__ float smu, srs;
    s = warpsum(s); sq = warpsum(sq);
    int w = tid >> 5, lane = tid & 31;
    if (lane == 0) { sh[w] = s; sh[8 + w] = sq; }
    __syncthreads();
    if (tid == 0) {
        float S = 0.f, SQ = 0.f;
#pragma unroll
        for (int i = 0; i < 8; i++) { S += sh[i]; SQ += sh[8 + i]; }
        float mu = S * (1.f / DIMM);
        float var = SQ * (1.f / DIMM) - mu * mu;
        smu = mu;
        srs = rsqrtf(var + 1e-5f);
    }
    __syncthreads();
    float mu = smu, rs = srs;
    float4 g = ((const float4*)lng)[tid];
    float4 b = ((const float4*)lnb)[tid];
    float y0 = (x.x - mu) * rs * g.x + b.x;
    float y1 = (x.y - mu) * rs * g.y + b.y;
    float y2 = (x.z - mu) * rs * g.z + b.z;
    float y3 = (x.w - mu) * rs * g.w + b.w;
    uint2 hv, lv;
    hsplit4(y0, y1, y2, y3, hv, lv);
    ((uint2*)(d_xh[t] + (size_t)r * DIMM))[tid] = hv;
    ((uint2*)(d_xl[t] + (size_t)r * DIMM))[tid] = lv;
}

// =====================================================================
//  big GEMM: C[8192x1024] = A @ B^T, fp16x2 (Ah,Al vs Bh).
//  CTA tile 128x256, K-blocks of 64, 3-stage cp.async pipeline.
// =====================================================================
static constexpr int MM_STAGE = 65536;
static constexpr int MM_SMEM = 3 * MM_STAGE;   // 196608

__device__ __forceinline__ void mm_fill(uint32_t sb, int s, int kb,
                                        const char* const* gsrc, int tid) {
    uint32_t st = sb + s * MM_STAGE;
#pragma unroll
    for (int p = 0; p < 2; p++) {       // A hi/lo: 128 rows x 128B
        uint32_t base = st + p * 16384;
        const char* src = gsrc[p] + kb * 128;
#pragma unroll
        for (int i = 0; i < 4; i++) {
            int id = tid + i * 256;
            int row = id >> 3, c = id & 7;
            uint32_t sw = (uint32_t)((c ^ (row & 7)) << 4);
            cp16(base + row * 128 + sw, src + (size_t)row * 2048 + c * 16);
        }
    }
    {                                    // B hi: 256 rows x 128B
        uint32_t base = st + 32768;
        const char* src = gsrc[2] + kb * 128;
#pragma unroll
        for (int i = 0; i < 8; i++) {
            int id = tid + i * 256;
            int row = id >> 3, c = id & 7;
            uint32_t sw = (uint32_t)((c ^ (row & 7)) << 4);
            cp16(base + row * 128 + sw, src + (size_t)row * 2048 + c * 16);
        }
    }
    asm volatile("cp.async.commit_group;\n");
}

__device__ __forceinline__ void mm_compute(uint32_t st, float acc[4][8][4],
                                           int wm, int wn, int lane) {
    uint32_t bAh = st, bAl = st + 16384, bBh = st + 32768;
    int la7 = lane & 7;
#pragma unroll
    for (int kc = 0; kc < 4; kc++) {
        uint32_t ah[4][4], al[4][4];
        int chA = kc * 2 + (lane >> 4);
#pragma unroll
        for (int mi = 0; mi < 4; mi++) {
            int row = wm * 64 + mi * 16 + la7 + ((lane >> 3) & 1) * 8;
            uint32_t off = (uint32_t)row * 128 + (uint32_t)((chA ^ (row & 7)) << 4);
            ldsm_x4(ah[mi], bAh + off);
            ldsm_x4(al[mi], bAl + off);
        }
        int chB = kc * 2 + ((lane >> 3) & 1);
#pragma unroll
        for (int nhf = 0; nhf < 2; nhf++) {
            uint32_t bh[2][4];
#pragma unroll
            for (int nh = 0; nh < 2; nh++) {
                int row = wn * 64 + (nhf * 2 + nh) * 16 + la7 + (lane >> 4) * 8;
                uint32_t off = (uint32_t)row * 128 + (uint32_t)((chB ^ (row & 7)) << 4);
                ldsm_x4(bh[nh], bBh + off);
            }
#pragma unroll
            for (int mi = 0; mi < 4; mi++)
#pragma unroll
                for (int nj = 0; nj < 4; nj++)
                    mma_f16(acc[mi][nhf * 4 + nj], ah[mi], &bh[nj >> 1][2 * (nj & 1)]);
#pragma unroll
            for (int mi = 0; mi < 4; mi++)
#pragma unroll
                for (int nj = 0; nj < 4; nj++)
                    mma_f16(acc[mi][nhf * 4 + nj], al[mi], &bh[nj >> 1][2 * (nj & 1)]);
        }
    }
}

template <bool OUTF32>
__device__ __forceinline__ void mm_body(
    const __half* __restrict__ Ah, const __half* __restrict__ Al,
    const __half* __restrict__ Bh,
    float* __restrict__ C, const float* __restrict__ bias,
    __half* __restrict__ SH, __half* __restrict__ SL) {
    extern __shared__ char smem[];
    int tid = threadIdx.x, lane = tid & 31, wid = tid >> 5;
    int wm = wid >> 2, wn = wid & 3;
    int m0 = blockIdx.y * 128, n0 = blockIdx.x * 256;
    uint32_t sb = smem_u32(smem);

    const char* gsrc[3];
    gsrc[0] = (const char*)(Ah + (size_t)m0 * DIMM);
    gsrc[1] = (const char*)(Al + (size_t)m0 * DIMM);
    gsrc[2] = (const char*)(Bh + (size_t)n0 * DIMM);

    float acc[4][8][4];
#pragma unroll
    for (int i = 0; i < 4; i++)
#pragma unroll
        for (int j = 0; j < 8; j++)
#pragma unroll
            for (int q = 0; q < 4; q++) acc[i][j][q] = 0.f;

    mm_fill(sb, 0, 0, gsrc, tid);
    mm_fill(sb, 1, 1, gsrc, tid);

    for (int kb = 0; kb < 16; kb++) {
        if (kb < 15) asm volatile("cp.async.wait_group 1;\n");
        else         asm volatile("cp.async.wait_group 0;\n");
        __syncthreads();
        if (kb + 2 < 16) mm_fill(sb, (kb + 2) % 3, kb + 2, gsrc, tid);
        mm_compute(sb + (kb % 3) * MM_STAGE, acc, wm, wn, lane);
    }

#pragma unroll
    for (int mi = 0; mi < 4; mi++) {
        int r0 = m0 + wm * 64 + mi * 16 + (lane >> 2);
#pragma unroll
        for (int ni = 0; ni < 8; ni++) {
            int c = n0 + wn * 64 + ni * 8 + (lane & 3) * 2;
            float2 v0 = make_float2(acc[mi][ni][0], acc[mi][ni][1]);
            float2 v1 = make_float2(acc[mi][ni][2], acc[mi][ni][3]);
            if (OUTF32) {
                float b0 = bias[c], b1 = bias[c + 1];
                v0.x += b0; v0.y += b1;
                v1.x += b0; v1.y += b1;
                *(float2*)(C + (size_t)r0 * DIMM + c) = v0;
                *(float2*)(C + (size_t)(r0 + 8) * DIMM + c) = v1;
            } else {
                uint32_t hh, ll;
                hsplit2(v0.x, v0.y, hh, ll);
                *(uint32_t*)(SH + (size_t)r0 * DIMM + c) = hh;
                *(uint32_t*)(SL + (size_t)r0 * DIMM + c) = ll;
                hsplit2(v1.x, v1.y, hh, ll);
                *(uint32_t*)(SH + (size_t)(r0 + 8) * DIMM + c) = hh;
                *(uint32_t*)(SL + (size_t)(r0 + 8) * DIMM + c) = ll;
            }
        }
    }
}

__global__ void __launch_bounds__(256, 1) mm_proj_kernel() {
    int which = blockIdx.z;
    if (which == 0)
        mm_body<false>(d_xh[0], d_xl[0], d_wih, nullptr, nullptr, d_fqh, d_fql);
    else if (which == 1)
        mm_body<false>(d_xh[1], d_xl[1], d_wih, nullptr, nullptr, d_fkh, d_fkl);
    else
        mm_body<false>(d_xh[2], d_xl[2], d_wih, nullptr, nullptr, d_fvh, d_fvl);
}

__global__ void __launch_bounds__(256, 1) mm_out_kernel(const float* __restrict__ bias,
                                                        float* __restrict__ out) {
    mm_body<true>(d_oh, d_ol, d_woh, out, bias, nullptr, nullptr);
}

// =====================================================================
//  merged per-(head,row) stats (hi-only) + centered-q hi + ikn-scaled v hi
// =====================================================================
__global__ void statsprep_kernel() {
    int r = blockIdx.x;
    int tid = threadIdx.x;
    int w = tid >> 5, lane = tid & 31;
    size_t base = (size_t)r * DIMM + w * DD + lane * 4;

    // f_q: stats from hi + centered hi
    {
        uint2 uh = *(const uint2*)(d_fqh + base);
        float2 a0 = __half22float2(*(__half2*)&uh.x), a1 = __half22float2(*(__half2*)&uh.y);
        float x0 = a0.x, x1 = a0.y, x2 = a1.x, x3 = a1.y;
        float s = warpsum(x0 + x1 + x2 + x3);
        float sq = warpsum(x0 * x0 + x1 * x1 + x2 * x2 + x3 * x3);
        float mean = s * (1.f / DD);
        float var = (sq - s * s * (1.f / DD)) * (1.f / (DD - 1));
        if (lane == 0) {
            d_iqn[w][r] = rsqrtf(sq);
            d_qr[w][r] = 2.f * fminf(var, 1.f) / (var + 1.f);
        }
        uint2 hv;
        hv.x = h2u(__floats2half2_rn(x0 - mean, x1 - mean));
        hv.y = h2u(__floats2half2_rn(x2 - mean, x3 - mean));
        *(uint2*)(d_qch + base) = hv;
    }
    // f_k: stats from hi (ikn broadcast to all lanes)
    float ikn;
    {
        uint2 uh = *(const uint2*)(d_fkh + base);
        float2 a0 = __half22float2(*(__half2*)&uh.x), a1 = __half22float2(*(__half2*)&uh.y);
        float k0 = a0.x, k1 = a0.y, k2 = a1.x, k3 = a1.y;
        float s = warpsum(k0 + k1 + k2 + k3);
        float sq = warpsum(k0 * k0 + k1 * k1 + k2 * k2 + k3 * k3);
        ikn = rsqrtf(sq);
        float var = (sq - s * s * (1.f / DD)) * (1.f / (DD - 1));
        if (lane == 0) {
            d_ikn[w][r] = ikn;
            d_kr[w][r] = 2.f * fminf(var, 1.f) / (var + 1.f);
        }
    }
    // f_v -> vt = fv * ikn, hi only
    {
        uint2 uh = *(const uint2*)(d_fvh + base);
        uint2 ul = *(const uint2*)(d_fvl + base);
        float2 a0 = __half22float2(*(__half2*)&uh.x), a1 = __half22float2(*(__half2*)&uh.y);
        float2 b0 = __half22float2(*(__half2*)&ul.x), b1 = __half22float2(*(__half2*)&ul.y);
        float v0 = (a0.x + b0.x) * ikn, v1 = (a0.y + b0.y) * ikn;
        float v2 = (a1.x + b1.x) * ikn, v3 = (a1.y + b1.y) * ikn;
        uint2 hv;
        hv.x = h2u(__floats2half2_rn(v0, v1));
        hv.y = h2u(__floats2half2_rn(v2, v3));
        *(uint2*)(d_vth + base) = hv;
    }
}

// =====================================================================
//  mid_kernel bodies: kvm (tc 2-term), gram1 (tc 1-term), gpart, gv
//  32-row K-chunks, double-buffered, 2 CTAs/SM.
// =====================================================================
static constexpr int ATB_MAT = 32 * 272;       // 8704
static constexpr int KVM_STG = 3 * ATB_MAT;    // 26112 (fkh, fkl, vth)
static constexpr int MID_SMEM = 2 * KVM_STG;   // 52224

__device__ __forceinline__ void kvm_fill(uint32_t sb, int s, int c,
        const __half* Ah, const __half* Al, const __half* Bh) {
    int tid = threadIdx.x;
    const __half* srcs[3] = {Ah, Al, Bh};
#pragma unroll
    for (int p = 0; p < 3; p++) {
        uint32_t base = sb + s * KVM_STG + p * ATB_MAT;
        const __half* src = srcs[p];
#pragma unroll
        for (int i = 0; i < 2; i++) {
            int id = tid + i * 256;
            int row = id >> 4, c16 = id & 15;
            cp16(base + row * 272 + c16 * 16,
                 src + (size_t)(c * 32 + row) * DIMM + c16 * 8);
        }
    }
    asm volatile("cp.async.commit_group;\n");
}

__device__ void kvm_body(char* smem, int blk) {
    int h = blk >> 4, qi = blk & 15;
    size_t off = (size_t)(qi * NN) * DIMM + h * DD;
    uint32_t sb = smem_u32(smem);
    int tid = threadIdx.x, lane = tid & 31, wid = tid >> 5;
    int wm = wid >> 2, wn = wid & 3;
    int la7 = lane & 7;
    float acc[4][4][4];
#pragma unroll
    for (int i = 0; i < 4; i++)
#pragma unroll
        for (int j = 0; j < 4; j++)
#pragma unroll
            for (int q = 0; q < 4; q++) acc[i][j][q] = 0.f;

    kvm_fill(sb, 0, 0, d_fkh + off, d_fkl + off, d_vth + off);
    int arow = ((lane >> 4) << 3) + la7;
    int acol = (((lane >> 3) & 1) << 3);
    int brow = (((lane >> 3) & 1) << 3) + la7;
    int bcol = ((lane >> 4) << 3);
    for (int c = 0; c < 16; c++) {
        asm volatile("cp.async.wait_group 0;\n");
        __syncthreads();
        if (c + 1 < 16)
            kvm_fill(sb, (c + 1) & 1, c + 1, d_fkh + off, d_fkl + off, d_vth + off);
        uint32_t bA  = sb + (c & 1) * KVM_STG;
        uint32_t bAl = bA + ATB_MAT;
        uint32_t bB  = bA + 2 * ATB_MAT;
#pragma unroll
        for (int kc = 0; kc < 2; kc++) {
            uint32_t ah[4][4], al[4][4];
#pragma unroll
            for (int mi = 0; mi < 4; mi++) {
                uint32_t o = (uint32_t)(kc * 16 + arow) * 272 +
                             (uint32_t)(wm * 64 + mi * 16 + acol) * 2;
                ldsm_x4_t(ah[mi], bA + o);
                ldsm_x4_t(al[mi], bAl + o);
            }
            uint32_t bh[4][2];
#pragma unroll
            for (int nh = 0; nh < 2; nh++) {
                uint32_t o = (uint32_t)(kc * 16 + brow) * 272 +
                             (uint32_t)(wn * 32 + nh * 16 + bcol) * 2;
                uint32_t r[4];
                ldsm_x4_t(r, bB + o);
                bh[2 * nh][0] = r[0]; bh[2 * nh][1] = r[1];
                bh[2 * nh + 1][0] = r[2]; bh[2 * nh + 1][1] = r[3];
            }
#pragma unroll
            for (int mi = 0; mi < 4; mi++)
#pragma unroll
                for (int ni = 0; ni < 4; ni++) mma_f16(acc[mi][ni], ah[mi], bh[ni]);
#pragma unroll
            for (int mi = 0; mi < 4; mi++)
#pragma unroll
                for (int ni = 0; ni < 4; ni++) mma_f16(acc[mi][ni], al[mi], bh[ni]);
        }
    }
    __half* Oh = d_Mh + (size_t)blk * DD * DD;
#pragma unroll
    for (int mi = 0; mi < 4; mi++) {
        int d0 = wm * 64 + mi * 16 + (lane >> 2);
#pragma unroll
        for (int ni = 0; ni < 4; ni++) {
            int e = wn * 32 + ni * 8 + (lane & 3) * 2;
            *(uint32_t*)(Oh + d0 * DD + e) =
                h2u(__floats2half2_rn(acc[mi][ni][0], acc[mi][ni][1]));
            *(uint32_t*)(Oh + (d0 + 8) * DD + e) =
                h2u(__floats2half2_rn(acc[mi][ni][2], acc[mi][ni][3]));
        }
    }
}

__device__ void gram1_body(char* smem, int ch, int h) {
    const __half* A = d_qch + (size_t)(ch * 512) * DIMM + h * DD;
    uint32_t sb = smem_u32(smem);
    int tid = threadIdx.x, lane = tid & 31, wid = tid >> 5;
    int wm = wid >> 2, wn = wid & 3;
    int la7 = lane & 7;
    float acc[4][4][4];
#pragma unroll
    for (int i = 0; i < 4; i++)
#pragma unroll
        for (int j = 0; j < 4; j++)
#pragma unroll
            for (int q = 0; q < 4; q++) acc[i][j][q] = 0.f;

    auto fill = [&](int s, int c) {
#pragma unroll
        for (int i = 0; i < 2; i++) {
            int id = tid + i * 256;
            int row = id >> 4, c16 = id & 15;
            cp16(sb + s * ATB_MAT + row * 272 + c16 * 16,
                 A + (size_t)(c * 32 + row) * DIMM + c16 * 8);
        }
        asm volatile("cp.async.commit_group;\n");
    };

    fill(0, 0);
    int arow = ((lane >> 4) << 3) + la7;
    int acol = (((lane >> 3) & 1) << 3);
    int brow = (((lane >> 3) & 1) << 3) + la7;
    int bcol = ((lane >> 4) << 3);
    for (int c = 0; c < 16; c++) {
        asm volatile("cp.async.wait_group 0;\n");
        __syncthreads();
        if (c + 1 < 16) fill((c + 1) & 1, c + 1);
        uint32_t bA = sb + (c & 1) * ATB_MAT;
#pragma unroll
        for (int kc = 0; kc < 2; kc++) {
            uint32_t ah[4][4];
#pragma unroll
            for (int mi = 0; mi < 4; mi++) {
                uint32_t o = (uint32_t)(kc * 16 + arow) * 272 +
                             (uint32_t)(wm * 64 + mi * 16 + acol) * 2;
                ldsm_x4_t(ah[mi], bA + o);
            }
            uint32_t bh[4][2];
#pragma unroll
            for (int nh = 0; nh < 2; nh++) {
                uint32_t o = (uint32_t)(kc * 16 + brow) * 272 +
                             (uint32_t)(wn * 32 + nh * 16 + bcol) * 2;
                uint32_t r[4];
                ldsm_x4_t(r, bA + o);
                bh[2 * nh][0] = r[0]; bh[2 * nh][1] = r[1];
                bh[2 * nh + 1][0] = r[2]; bh[2 * nh + 1][1] = r[3];
            }
#pragma unroll
            for (int mi = 0; mi < 4; mi++)
#pragma unroll
                for (int ni = 0; ni < 4; ni++) mma_f16(acc[mi][ni], ah[mi], bh[ni]);
        }
    }
    float* Cf = d_Cpart[h * GCH + ch];
#pragma unroll
    for (int mi = 0; mi < 4; mi++) {
        int d0 = wm * 64 + mi * 16 + (lane >> 2);
#pragma unroll
        for (int ni = 0; ni < 4; ni++) {
            int e = wn * 32 + ni * 8 + (lane & 3) * 2;
            *(float2*)(Cf + d0 * DD + e) = make_float2(acc[mi][ni][0], acc[mi][ni][1]);
            *(float2*)(Cf + (d0 + 8) * DD + e) = make_float2(acc[mi][ni][2], acc[mi][ni][3]);
        }
    }
}

__device__ void gpart_body(int b) {
    int r0 = b * 32;
    int t = threadIdx.x;
    float2 sq0 = {0.f, 0.f}, sq1 = {0.f, 0.f};
    float2 sk0 = {0.f, 0.f}, sk1 = {0.f, 0.f};
    for (int row = 0; row < 32; row++) {
        const __half2* fq = (const __half2*)(d_fqh + (size_t)(r0 + row) * DIMM);
        const __half2* fk = (const __half2*)(d_fkh + (size_t)(r0 + row) * DIMM);
        float2 a = __half22float2(fq[t]);       sq0.x += a.x; sq0.y += a.y;
        float2 c = __half22float2(fq[t + 256]); sq1.x += c.x; sq1.y += c.y;
        float2 e = __half22float2(fk[t]);       sk0.x += e.x; sk0.y += e.y;
        float2 f = __half22float2(fk[t + 256]); sk1.x += f.x; sk1.y += f.y;
    }
    d_gpart[b][2 * t] = sq0.x;       d_gpart[b][2 * t + 1] = sq0.y;
    d_gpart[b][512 + 2 * t] = sq1.x; d_gpart[b][512 + 2 * t + 1] = sq1.y;
    d_gpart[b][DIMM + 2 * t] = sk0.x;       d_gpart[b][DIMM + 2 * t + 1] = sk0.y;
    d_gpart[b][DIMM + 512 + 2 * t] = sk1.x; d_gpart[b][DIMM + 512 + 2 * t + 1] = sk1.y;
}

__device__ void gv_body(int blk) {
    int h = blk >> 4, qi = blk & 15;
    int r0 = qi * NN;
    int tid = threadIdx.x;
    int e = tid & 127, half = tid >> 7;
    __shared__ float kr[NN];
    __shared__ float part[2][DD];
    for (int i = tid; i < NN; i += 256) kr[i] = d_kr[h][r0 + i];
    __syncthreads();
    float a0 = 0.f, a1 = 0.f;
    int nb = half * 256;
    const __half* vh = d_fvh + (size_t)(r0 + nb) * DIMM + h * DD + e;
    const __half* vl = d_fvl + (size_t)(r0 + nb) * DIMM + h * DD + e;
#pragma unroll 2
    for (int n = 0; n < 256; n += 2) {
        a0 += kr[nb + n] * (__half2float(vh[(size_t)n * DIMM]) + __half2float(vl[(size_t)n * DIMM]));
        a1 += kr[nb + n + 1] * (__half2float(vh[(size_t)(n + 1) * DIMM]) + __half2float(vl[(size_t)(n + 1) * DIMM]));
    }
    part[half][e] = a0 + a1;
    __syncthreads();
    if (half == 0) d_gv[blk][e] = part[0][e] + part[1][e];
}

// mid_kernel: 0..127 kvm | 128..255 gram1 | 256..511 gpart | 512..639 gv
__global__ void __launch_bounds__(256, 2) mid_kernel() {
    extern __shared__ char smem[];
    int b = blockIdx.x;
    if (b < 128) kvm_body(smem, b);
    else if (b < 256) { int i = b - 128; gram1_body(smem, i & 15, i >> 4); }
    else if (b < 512) gpart_body(b - 256);
    else gv_body(b - 512);
}

// ---------------- creduce1: gram partial reduce ----------------
__global__ void creduce1_kernel() {
    int ch = blockIdx.x;
    int h = blockIdx.y;
    int tid = threadIdx.x;
    float ssum = 0.f;
#pragma unroll
    for (int u = 0; u < 4; u++) {
        int i = ch * 1024 + tid + u * 256;
        float c = 0.f;
#pragma unroll
        for (int p = 0; p < GCH; p++) c += d_Cpart[h * GCH + p][i];
        if ((i / DD) != (i % DD)) ssum += c * c;
    }
    __shared__ float sh[8];
    ssum = warpsum(ssum);
    int w = tid >> 5, lane = tid & 31;
    if (lane == 0) sh[w] = ssum;
    __syncthreads();
    if (tid == 0) {
        float S = 0.f;
#pragma unroll
        for (int i = 0; i < 8; i++) S += sh[i];
        d_cred[h][ch] = S;
    }
}

// ---------------- weight-predictor MLP (+ inline creduce2) ----------------
__global__ void wp_kernel(const float* __restrict__ w1, const float* __restrict__ b1,
                          const float* __restrict__ lng, const float* __restrict__ lnb,
                          const float* __restrict__ w2, const float* __restrict__ b2) {
    __shared__ float qg[DIMM], kg[DIMM];
    __shared__ float h1[HH][DD];
    __shared__ float logits[HH][3];
    __shared__ float sdsc[HH];
    int tid = threadIdx.x;
    if (tid < 8) {
        float S = 0.f;
#pragma unroll
        for (int i = 0; i < 16; i++) S += d_cred[tid][i];
        float fro = sqrtf(S) * (1.f / RTOT);
        float score = fro * (1.f / (128.f * 128.f));
        sdsc[tid] = expf(-5.f * score);
    }
    for (int i = tid; i < DIMM; i += 256) {
        float s = 0.f, s2 = 0.f;
        for (int b = 0; b < 256; b++) { s += d_gpart[b][i]; s2 += d_gpart[b][DIMM + i]; }
        qg[i] = s * (1.f / RTOT);
        kg[i] = s2 * (1.f / RTOT);
    }
    __syncthreads();
    for (int idx = tid; idx < HH * DD; idx += 256) {
        int h = idx / DD, i = idx % DD;
        float s = b1[i];
        const float* wr = w1 + i * 256;
#pragma unroll 4
        for (int j = 0; j < 128; j++) s += qg[h * 128 + j] * wr[j];
#pragma unroll 4
        for (int j = 0; j < 128; j++) s += kg[h * 128 + j] * wr[128 + j];
        h1[h][i] = s;
    }
    __syncthreads();
    int w = tid >> 5, lane = tid & 31;
    if (w < 8) {
        float s = 0.f, sq = 0.f;
        for (int i = lane; i < DD; i += 32) { float v = h1[w][i]; s += v; sq += v * v; }
        s = warpsum(s); sq = warpsum(sq);
        float mean = s * (1.f / DD);
        float var = sq * (1.f / DD) - mean * mean;
        float rs = rsqrtf(var + 1e-5f);
        for (int i = lane; i < DD; i += 32) {
            float vv = (h1[w][i] - mean) * rs * lng[i] + lnb[i];
            h1[w][i] = fmaxf(vv, 0.f);
        }
    }
    __syncthreads();
    if (tid < 24) {
        int h = tid / 3, c = tid % 3;
        float s = b2[c];
        const float* wr = w2 + c * DD;
        for (int i = 0; i < DD; i++) s += h1[h][i] * wr[i];
        logits[h][c] = s;
    }
    __syncthreads();
    if (tid < 8) {
        float a = logits[tid][0], b = logits[tid][1], c = logits[tid][2];
        float m = fmaxf(a, fmaxf(b, c));
        float ea = expf(a - m), eb = expf(b - m), ec = expf(c - m);
        float inv = 1.f / (ea + eb + ec);
        d_s1[tid] = ea * inv + eb * inv * sdsc[tid];
        d_wws[tid] = ec * inv;
    }
}

// =====================================================================
//  attout: att[128x128] = f_q @ Mh (2-term: Ah,Al vs Mh), + rank-1 term
// =====================================================================
static constexpr int AO_MAT = 128 * 272;       // 34816
static constexpr int AO_SMEM = 3 * AO_MAT;     // 104448

__global__ void __launch_bounds__(256, 2) attout_tc_kernel() {
    int blk = blockIdx.y, mt = blockIdx.x;
    int h = blk >> 4, qi = blk & 15;
    int r0g = qi * NN + mt * 128;
    int co = h * DD;
    extern __shared__ char smem[];
    uint32_t sb = smem_u32(smem);
    int tid = threadIdx.x, lane = tid & 31, wid = tid >> 5;
    int wm = wid >> 2, wn = wid & 3;
    int la7 = lane & 7;

    {
        const __half* Asrc[2] = {d_fqh, d_fql};
#pragma unroll
        for (int p = 0; p < 2; p++) {
            uint32_t base = sb + p * AO_MAT;
            const __half* src = Asrc[p] + (size_t)r0g * DIMM + co;
#pragma unroll
            for (int i = 0; i < 8; i++) {
                int id = tid + i * 256;
                int row = id >> 4, c16 = id & 15;
                cp16(base + row * 272 + c16 * 16, src + (size_t)row * DIMM + c16 * 8);
            }
        }
        {
            uint32_t base = sb + 2 * AO_MAT;
            const __half* src = d_Mh + (size_t)blk * DD * DD;
#pragma unroll
            for (int i = 0; i < 8; i++) {
                int id = tid + i * 256;
                int row = id >> 4, c16 = id & 15;
                cp16(base + row * 272 + c16 * 16, src + row * DD + c16 * 8);
            }
        }
        asm volatile("cp.async.commit_group;\ncp.async.wait_group 0;\n");
        __syncthreads();
    }

    float acc[4][4][4];
#pragma unroll
    for (int i = 0; i < 4; i++)
#pragma unroll
        for (int j = 0; j < 4; j++)
#pragma unroll
            for (int q = 0; q < 4; q++) acc[i][j][q] = 0.f;

    uint32_t bA  = sb;
    uint32_t bAl = sb + AO_MAT;
    uint32_t bB  = sb + 2 * AO_MAT;
    int brow = (((lane >> 3) & 1) << 3) + la7;
    int bcol = ((lane >> 4) << 3);
#pragma unroll
    for (int kc = 0; kc < 8; kc++) {
        uint32_t ah[4][4], al[4][4];
#pragma unroll
        for (int mi = 0; mi < 4; mi++) {
            uint32_t off = (uint32_t)(wm * 64 + mi * 16 + (lane & 15)) * 272 +
                           (uint32_t)(kc * 16 + ((lane >> 4) << 3)) * 2;
            ldsm_x4(ah[mi], bA + off);
            ldsm_x4(al[mi], bAl + off);
        }
        uint32_t bh[4][2];
#pragma unroll
        for (int nh = 0; nh < 2; nh++) {
            uint32_t off = (uint32_t)(kc * 16 + brow) * 272 +
                           (uint32_t)(wn * 32 + nh * 16 + bcol) * 2;
            uint32_t r[4];
            ldsm_x4_t(r, bB + off);
            bh[2 * nh][0] = r[0]; bh[2 * nh][1] = r[1];
            bh[2 * nh + 1][0] = r[2]; bh[2 * nh + 1][1] = r[3];
        }
#pragma unroll
        for (int mi = 0; mi < 4; mi++)
#pragma unroll
            for (int ni = 0; ni < 4; ni++) mma_f16(acc[mi][ni], ah[mi], bh[ni]);
#pragma unroll
        for (int mi = 0; mi < 4; mi++)
#pragma unroll
            for (int ni = 0; ni < 4; ni++) mma_f16(acc[mi][ni], al[mi], bh[ni]);
    }

    float s1 = d_s1[h], ww = d_wws[h];
#pragma unroll
    for (int mi = 0; mi < 4; mi++) {
        int rA = r0g + wm * 64 + mi * 16 + (lane >> 2);
        int rB = rA + 8;
        float f1a = s1 * d_iqn[h][rA], f2a = ww * d_qr[h][rA];
        float f1b = s1 * d_iqn[h][rB], f2b = ww * d_qr[h][rB];
#pragma unroll
        for (int ni = 0; ni < 4; ni++) {
            int c = wn * 32 + ni * 8 + (lane & 3) * 2;
            float g0 = d_gv[blk][c], g1 = d_gv[blk][c + 1];
            float o0 = f1a * acc[mi][ni][0] + f2a * g0;
            float o1 = f1a * acc[mi][ni][1] + f2a * g1;
            float o2 = f1b * acc[mi][ni][2] + f2b * g0;
            float o3 = f1b * acc[mi][ni][3] + f2b * g1;
            uint32_t hh, ll;
            hsplit2(o0, o1, hh, ll);
            *(uint32_t*)(d_oh + (size_t)rA * DIMM + co + c) = hh;
            *(uint32_t*)(d_ol + (size_t)rA * DIMM + co + c) = ll;
            hsplit2(o2, o3, hh, ll);
            *(uint32_t*)(d_oh + (size_t)rB * DIMM + co + c) = hh;
            *(uint32_t*)(d_ol + (size_t)rB * DIMM + co + c) = ll;
        }
    }
}

// ---------------- launch ----------------
extern "C" void kernel_launch(void* const* d_in, const int* in_sizes, int n_in,
                              void* d_out, int out_size) {
    const float* q      = (const float*)d_in[0];
    const float* k      = (const float*)d_in[1];
    const float* v      = (const float*)d_in[2];
    const float* ln_g   = (const float*)d_in[3];
    const float* ln_b   = (const float*)d_in[4];
    const float* w_in   = (const float*)d_in[5];
    const float* wp_w1  = (const float*)d_in[6];
    const float* wp_b1  = (const float*)d_in[7];
    const float* wp_lng = (const float*)d_in[8];
    const float* wp_lnb = (const float*)d_in[9];
    const float* wp_w2  = (const float*)d_in[10];
    const float* wp_b2  = (const float*)d_in[11];
    const float* w_out  = (const float*)d_in[12];
    const float* b_out  = (const float*)d_in[13];
    float* out = (float*)d_out;

    cudaFuncSetAttribute(mm_proj_kernel, cudaFuncAttributeMaxDynamicSharedMemorySize, MM_SMEM);
    cudaFuncSetAttribute(mm_out_kernel, cudaFuncAttributeMaxDynamicSharedMemorySize, MM_SMEM);
    cudaFuncSetAttribute(mid_kernel, cudaFuncAttributeMaxDynamicSharedMemorySize, MID_SMEM);
    cudaFuncSetAttribute(attout_tc_kernel, cudaFuncAttributeMaxDynamicSharedMemorySize, AO_SMEM);

    lnwconv_kernel<<<3 * RTOT + 2 * DIMM, 256>>>(q, k, v, ln_g, ln_b, w_in, w_out);

    dim3 gproj(DIMM / 256, RTOT / 128, 3);   // (4, 64, 3)
    mm_proj_kernel<<<gproj, 256, MM_SMEM>>>();

    statsprep_kernel<<<RTOT, 256>>>();

    mid_kernel<<<640, 256, MID_SMEM>>>();

    dim3 gcr1(16, HH);
    creduce1_kernel<<<gcr1, 256>>>();
    wp_kernel<<<1, 256>>>(wp_w1, wp_b1, wp_lng, wp_lnb, wp_w2, wp_b2);

    dim3 gatt(4, HH * QBB);
    attout_tc_kernel<<<gatt, 256, AO_SMEM>>>();

    dim3 gout(DIMM / 256, RTOT / 128);       // (4, 64)
    mm_out_kernel<<<gout, 256, MM_SMEM>>>(b_out, out);
}